// round 4
// baseline (speedup 1.0000x reference)
#include <cuda_runtime.h>
#include <math.h>

// Problem constants (fixed by the reference)
#define BATCH 8192
#define DDIM  512
#define HDIM  2048
#define DT_F  0.1f
#define N_STEPS 10

// ---------------------------------------------------------------------------
// Scratch in __device__ globals (no allocation allowed in kernel_launch).
// g_y:    current state y                [BATCH, DDIM]   16 MB
// g_ytmp: y + dt*k1                      [BATCH, DDIM]   16 MB
// g_k1:   k1 slope                       [BATCH, DDIM]   16 MB
// g_h:    hidden tanh activations        [BATCH, HDIM]   64 MB
// ---------------------------------------------------------------------------
__device__ float g_y   [(size_t)BATCH * DDIM];
__device__ float g_ytmp[(size_t)BATCH * DDIM];
__device__ float g_k1  [(size_t)BATCH * DDIM];
__device__ float g_h   [(size_t)BATCH * HDIM];

// ---------------------------------------------------------------------------
// Copy kernel: y0 -> g_y (vectorized)
// ---------------------------------------------------------------------------
__global__ void copy_f4(const float4* __restrict__ src, float4* __restrict__ dst, int n4) {
    int i = blockIdx.x * blockDim.x + threadIdx.x;
    if (i < n4) dst[i] = src[i];
}

// ---------------------------------------------------------------------------
// Tiled fp32 GEMM with fused epilogues.
//   C_acc = A[M,K] @ B[K,N]      (A row-major, B row-major)
// MODE 0:  Out[m,n]  = tanhf(acc + bias[n])                       (hidden layer)
// MODE 1:  k1 = acc + bias[n];  Out = k1;  Out2 = Yin + DT*k1     (k1 + Heun predictor)
// MODE 2:  k2 = acc + bias[n];  Out = Yin + 0.5*DT*(K1v + k2)     (Heun corrector)
//
// Block tile 128x128, K-tile 8, 256 threads, 8x8 per-thread microtile
// arranged as 2x2 quadrants of 4x4 (stride-64 split) for conflict-light smem.
// All dims are multiples of the tile sizes (8192, 2048, 512) -> no bounds checks.
// ---------------------------------------------------------------------------
template <int MODE>
__global__ void __launch_bounds__(256, 2) gemm_ep(
    const float* __restrict__ A,
    const float* __restrict__ B,
    const float* __restrict__ bias,
    const float* __restrict__ Yin,
    const float* __restrict__ K1v,
    float* __restrict__ Out,
    float* __restrict__ Out2,
    int M, int N, int K)
{
    __shared__ float As[8][132];   // padded: A stored transposed As[k][m]
    __shared__ float Bs[8][128];   // Bs[k][n]

    const int tid = threadIdx.x;
    const int tx  = tid & 15;      // 0..15 -> N direction
    const int ty  = tid >> 4;      // 0..15 -> M direction

    const int m_base = blockIdx.y * 128;
    const int n_base = blockIdx.x * 128;

    // global load mapping
    const int a_row = tid >> 1;           // 0..127
    const int a_col = (tid & 1) * 4;      // 0 or 4
    const int b_row = tid >> 5;           // 0..7
    const int b_col = (tid & 31) * 4;     // 0..124

    const float* Aptr = A + (size_t)(m_base + a_row) * K + a_col;
    const float* Bptr = B + (size_t)b_row * N + n_base + b_col;

    float acc[8][8];
#pragma unroll
    for (int i = 0; i < 8; i++)
#pragma unroll
        for (int j = 0; j < 8; j++) acc[i][j] = 0.f;

    const int kTiles = K >> 3;
    for (int kt = 0; kt < kTiles; kt++) {
        float4 av = *(const float4*)Aptr;
        float4 bv = *(const float4*)Bptr;

        As[a_col + 0][a_row] = av.x;
        As[a_col + 1][a_row] = av.y;
        As[a_col + 2][a_row] = av.z;
        As[a_col + 3][a_row] = av.w;
        *(float4*)&Bs[b_row][b_col] = bv;
        __syncthreads();

#pragma unroll
        for (int k = 0; k < 8; k++) {
            float a0[8], b0[8];
            *(float4*)&a0[0] = *(const float4*)&As[k][ty * 4];
            *(float4*)&a0[4] = *(const float4*)&As[k][64 + ty * 4];
            *(float4*)&b0[0] = *(const float4*)&Bs[k][tx * 4];
            *(float4*)&b0[4] = *(const float4*)&Bs[k][64 + tx * 4];
#pragma unroll
            for (int i = 0; i < 8; i++)
#pragma unroll
                for (int j = 0; j < 8; j++)
                    acc[i][j] = fmaf(a0[i], b0[j], acc[i][j]);
        }
        __syncthreads();

        Aptr += 8;
        Bptr += (size_t)8 * N;
    }

    // -------------------- epilogue --------------------
    const int rm[2] = { m_base + ty * 4, m_base + 64 + ty * 4 };
    const int cn[2] = { n_base + tx * 4, n_base + 64 + tx * 4 };

#pragma unroll
    for (int bi = 0; bi < 2; bi++) {
#pragma unroll
        for (int i = 0; i < 4; i++) {
            const int row = rm[bi] + i;
#pragma unroll
            for (int bj = 0; bj < 2; bj++) {
                const int col = cn[bj];
                const size_t off = (size_t)row * N + col;
                float4 bv = *(const float4*)&bias[col];
                float v[4];
                v[0] = acc[bi * 4 + i][bj * 4 + 0] + bv.x;
                v[1] = acc[bi * 4 + i][bj * 4 + 1] + bv.y;
                v[2] = acc[bi * 4 + i][bj * 4 + 2] + bv.z;
                v[3] = acc[bi * 4 + i][bj * 4 + 3] + bv.w;

                if (MODE == 0) {
                    float4 r;
                    r.x = tanhf(v[0]); r.y = tanhf(v[1]);
                    r.z = tanhf(v[2]); r.w = tanhf(v[3]);
                    *(float4*)&Out[off] = r;
                } else if (MODE == 1) {
                    float4 yv = *(const float4*)&Yin[off];
                    float4 k1r, yt;
                    k1r.x = v[0]; k1r.y = v[1]; k1r.z = v[2]; k1r.w = v[3];
                    yt.x = fmaf(DT_F, v[0], yv.x);
                    yt.y = fmaf(DT_F, v[1], yv.y);
                    yt.z = fmaf(DT_F, v[2], yv.z);
                    yt.w = fmaf(DT_F, v[3], yv.w);
                    *(float4*)&Out[off]  = k1r;
                    *(float4*)&Out2[off] = yt;
                } else {  // MODE == 2
                    float4 yv = *(const float4*)&Yin[off];
                    float4 kv = *(const float4*)&K1v[off];
                    float4 r;
                    const float h = 0.5f * DT_F;
                    r.x = fmaf(h, kv.x + v[0], yv.x);
                    r.y = fmaf(h, kv.y + v[1], yv.y);
                    r.z = fmaf(h, kv.z + v[2], yv.z);
                    r.w = fmaf(h, kv.w + v[3], yv.w);
                    *(float4*)&Out[off] = r;
                }
            }
        }
    }
}

// ---------------------------------------------------------------------------
// Launch: full Heun integration, 10 steps, 4 GEMMs per step.
// ---------------------------------------------------------------------------
extern "C" void kernel_launch(void* const* d_in, const int* in_sizes, int n_in,
                              void* d_out, int out_size)
{
    const float* y0 = (const float*)d_in[0];
    const float* W1 = (const float*)d_in[1];
    const float* b1 = (const float*)d_in[2];
    const float* W2 = (const float*)d_in[3];
    const float* b2 = (const float*)d_in[4];
    float* out = (float*)d_out;

    float *yv, *ytmp, *k1, *hbuf;
    cudaGetSymbolAddress((void**)&yv,   g_y);
    cudaGetSymbolAddress((void**)&ytmp, g_ytmp);
    cudaGetSymbolAddress((void**)&k1,   g_k1);
    cudaGetSymbolAddress((void**)&hbuf, g_h);

    // y = y0
    {
        int n4 = BATCH * DDIM / 4;
        copy_f4<<<(n4 + 255) / 256, 256>>>((const float4*)y0, (float4*)yv, n4);
    }

    const dim3 blk(256);
    const dim3 gridH(HDIM / 128, BATCH / 128);   // GEMM1: N=2048
    const dim3 gridD(DDIM / 128, BATCH / 128);   // GEMM2: N=512

    for (int s = 0; s < N_STEPS; s++) {
        // h = tanh(y @ W1 + b1)
        gemm_ep<0><<<gridH, blk>>>(yv, W1, b1, nullptr, nullptr, hbuf, nullptr,
                                   BATCH, HDIM, DDIM);
        // k1 = h @ W2 + b2 ; ytmp = y + dt*k1
        gemm_ep<1><<<gridD, blk>>>(hbuf, W2, b2, yv, nullptr, k1, ytmp,
                                   BATCH, DDIM, HDIM);
        // h = tanh(ytmp @ W1 + b1)
        gemm_ep<0><<<gridH, blk>>>(ytmp, W1, b1, nullptr, nullptr, hbuf, nullptr,
                                   BATCH, HDIM, DDIM);
        // y = y + 0.5*dt*(k1 + (h @ W2 + b2))   (last step writes d_out)
        float* ydst = (s == N_STEPS - 1) ? out : yv;
        gemm_ep<2><<<gridD, blk>>>(hbuf, W2, b2, yv, k1, ydst, nullptr,
                                   BATCH, DDIM, HDIM);
    }
}

// round 13
// speedup vs baseline: 2.4026x; 2.4026x over previous
#include <cuda_runtime.h>
#include <cuda_fp16.h>
#include <cstdint>
#include <math.h>

// Problem constants
#define BATCH 8192
#define DDIM  512
#define HDIM  2048
#define DT_F  0.1f
#define N_STEPS 10

// GEMM tiling
#define BM 128
#define BN 128
#define BK 32
#define STAGES 4
#define NTHREADS 256
#define STAGE_BYTES 32768              // A 16KB + B 16KB (hi+lo interleaved per row)
#define SMEM_BYTES (STAGES * STAGE_BYTES)   // 128 KB

// ---------------------------------------------------------------------------
// Scratch (__device__ globals). Half buffers backed by float4 for 16B align.
// ---------------------------------------------------------------------------
#define NY ((size_t)BATCH * DDIM)
#define NH ((size_t)BATCH * HDIM)
#define NW ((size_t)DDIM * HDIM)
__device__ float  g_y  [NY];            // y   (fp32, elementwise consumer)
__device__ float  g_k1 [NY];            // k1  (fp32)
__device__ float4 g_yh [NY / 8];        // y   hi (fp16)
__device__ float4 g_yl [NY / 8];        // y   lo
__device__ float4 g_yth[NY / 8];        // ytmp hi
__device__ float4 g_ytl[NY / 8];        // ytmp lo
__device__ float4 g_hh [NH / 8];        // h   hi
__device__ float4 g_hl [NH / 8];        // h   lo
__device__ float4 g_w1h[NW / 8];        // W1^T hi  [H][D]
__device__ float4 g_w1l[NW / 8];
__device__ float4 g_w2h[NW / 8];        // W2^T hi  [D][H]
__device__ float4 g_w2l[NW / 8];

// ---------------------------------------------------------------------------
// PTX helpers (baseline sm_80+ features only — valid for compute_103)
// ---------------------------------------------------------------------------
__device__ __forceinline__ uint32_t smem_u32(const void* p) {
    uint32_t a;
    asm("{ .reg .u64 t; cvta.to.shared.u64 t, %1; cvt.u32.u64 %0, t; }" : "=r"(a) : "l"(p));
    return a;
}
__device__ __forceinline__ void cp16(uint32_t dst, const void* src) {
    asm volatile("cp.async.cg.shared.global [%0], [%1], 16;" :: "r"(dst), "l"(src));
}
__device__ __forceinline__ void cp_commit() {
    asm volatile("cp.async.commit_group;" ::: "memory");
}
template <int N>
__device__ __forceinline__ void cp_wait() {
    asm volatile("cp.async.wait_group %0;" :: "n"(N) : "memory");
}
__device__ __forceinline__ uint32_t lds32(uint32_t addr) {
    uint32_t v;
    asm volatile("ld.shared.b32 %0, [%1];" : "=r"(v) : "r"(addr));
    return v;
}
// D(f32) += A(f16) * B(f16):  m16n8k16, A row-major, B col-major
__device__ __forceinline__ void mma_16816(float* c, const uint32_t* a, const uint32_t* b) {
    asm volatile(
        "mma.sync.aligned.m16n8k16.row.col.f32.f16.f16.f32 "
        "{%0,%1,%2,%3}, {%4,%5,%6,%7}, {%8,%9}, {%0,%1,%2,%3};"
        : "+f"(c[0]), "+f"(c[1]), "+f"(c[2]), "+f"(c[3])
        : "r"(a[0]), "r"(a[1]), "r"(a[2]), "r"(a[3]), "r"(b[0]), "r"(b[1]));
}

// smem tile addressing: row = 128 bytes = 8 x 16B chunks, chunk swizzled by row&7.
// chunks 0..3 = hi halfs (k 0..31), chunks 4..7 = lo halfs.
__device__ __forceinline__ uint32_t tile_addr(uint32_t base, int r, int ch) {
    return base + (uint32_t)r * 128u + ((uint32_t)(ch ^ (r & 7)) << 4);
}

__device__ __forceinline__ void write_hl(__half* Hi, __half* Lo, size_t off,
                                         float v0, float v1) {
    __half h0 = __float2half_rn(v0), h1 = __float2half_rn(v1);
    *(__half2*)(Hi + off) = __halves2half2(h0, h1);
    float l0 = v0 - __half2float(h0);
    float l1 = v1 - __half2float(h1);
    *(__half2*)(Lo + off) = __floats2half2_rn(l0, l1);
}

// ---------------------------------------------------------------------------
// Init kernels
// ---------------------------------------------------------------------------
__global__ void split_init(const float4* __restrict__ src, float* __restrict__ dstF,
                           __half* __restrict__ hi, __half* __restrict__ lo, int n4) {
    int i = blockIdx.x * blockDim.x + threadIdx.x;
    if (i >= n4) return;
    float4 v = src[i];
    *(float4*)(dstF + 4 * (size_t)i) = v;
    write_hl(hi, lo, 4 * (size_t)i,     v.x, v.y);
    write_hl(hi, lo, 4 * (size_t)i + 2, v.z, v.w);
}

// in [R][C] fp32  ->  out hi/lo [C][R] fp16
__global__ void transpose_split(const float* __restrict__ in,
                                __half* __restrict__ oh, __half* __restrict__ ol,
                                int R, int C) {
    __shared__ float t[32][33];
    int bx = blockIdx.x * 32, by = blockIdx.y * 32;
    int tx = threadIdx.x, ty = threadIdx.y;
#pragma unroll
    for (int j = 0; j < 32; j += 8)
        t[ty + j][tx] = in[(size_t)(by + ty + j) * C + bx + tx];
    __syncthreads();
#pragma unroll
    for (int j = 0; j < 32; j += 8) {
        float v = t[tx][ty + j];
        __half h = __float2half_rn(v);
        size_t off = (size_t)(bx + ty + j) * R + by + tx;
        oh[off] = h;
        ol[off] = __float2half_rn(v - __half2float(h));
    }
}

// ---------------------------------------------------------------------------
// fp16x3-split HMMA GEMM with fused epilogues.
//   acc(f32) = A[M,K] @ BT[N,K]^T,  A/B given as fp16 (hi, lo) pairs.
// MODE 0:  h = tanh(acc+bias)            -> OutHi/OutLo
// MODE 1:  k1 = acc+bias -> OutF;  ytmp = Yin + DT*k1 -> OutHi/OutLo
// MODE 2:  ynew = Yin + 0.5*DT*(K1v + acc+bias) -> OutF and OutHi/OutLo
// ---------------------------------------------------------------------------
template <int MODE>
__global__ void __launch_bounds__(NTHREADS) gemm_hmma(
    const __half* __restrict__ Ahi, const __half* __restrict__ Alo,
    const __half* __restrict__ Bhi, const __half* __restrict__ Blo,
    const float* __restrict__ bias,
    const float* __restrict__ Yin,  const float* __restrict__ K1v,
    float* __restrict__ OutF,
    __half* __restrict__ OutHi, __half* __restrict__ OutLo,
    int M, int Ntot, int K)
{
    extern __shared__ char smem[];
    const uint32_t sbase = smem_u32(smem);

    const int tid    = threadIdx.x;
    const int wid    = tid >> 5;
    const int lane   = tid & 31;
    const int g      = lane >> 2;     // 0..7
    const int tg     = lane & 3;      // 0..3
    const int warp_m = wid & 1;       // 2 warps in M  (64 rows each)
    const int warp_n = wid >> 1;      // 4 warps in N  (32 cols each)

    const int m_base = blockIdx.y * BM;
    const int n_base = blockIdx.x * BN;

    // ---- cp.async source pointers (this thread's 4 chunks per matrix) ----
    const int lr = tid >> 2;          // 0..63
    const int lc = tid & 3;           // 0..3 (16B k-chunk)
    const __half* a_h0 = Ahi + (size_t)(m_base + lr) * K + lc * 8;
    const __half* a_l0 = Alo + (size_t)(m_base + lr) * K + lc * 8;
    const __half* b_h0 = Bhi + (size_t)(n_base + lr) * K + lc * 8;
    const __half* b_l0 = Blo + (size_t)(n_base + lr) * K + lc * 8;
    const size_t rstep = (size_t)64 * K;

    float acc[4][4][4];
#pragma unroll
    for (int i = 0; i < 4; i++)
#pragma unroll
        for (int j = 0; j < 4; j++)
#pragma unroll
            for (int q = 0; q < 4; q++) acc[i][j][q] = 0.f;

    const int nch = K / BK;

    // loader: 8 cp.async of 16B per thread per chunk
#define LOAD_CHUNK(KT, SLOT)                                                   \
    do {                                                                       \
        const uint32_t st = sbase + (uint32_t)(SLOT) * STAGE_BYTES;            \
        const uint32_t sb = st + 16384;                                        \
        const size_t ko = (size_t)(KT) * BK;                                   \
        cp16(tile_addr(st, lr,      lc    ), a_h0 + ko);                       \
        cp16(tile_addr(st, lr + 64, lc    ), a_h0 + ko + rstep);               \
        cp16(tile_addr(st, lr,      lc + 4), a_l0 + ko);                       \
        cp16(tile_addr(st, lr + 64, lc + 4), a_l0 + ko + rstep);               \
        cp16(tile_addr(sb, lr,      lc    ), b_h0 + ko);                       \
        cp16(tile_addr(sb, lr + 64, lc    ), b_h0 + ko + rstep);               \
        cp16(tile_addr(sb, lr,      lc + 4), b_l0 + ko);                       \
        cp16(tile_addr(sb, lr + 64, lc + 4), b_l0 + ko + rstep);               \
    } while (0)

    // prologue: fill STAGES-1 stages
#pragma unroll
    for (int s = 0; s < STAGES - 1; s++) {
        LOAD_CHUNK(s, s);
        cp_commit();
    }

    for (int kt = 0; kt < nch; kt++) {
        cp_wait<STAGES - 2>();
        __syncthreads();

        // issue loads for chunk kt+STAGES-1 into the slot freed last iteration
        if (kt + STAGES - 1 < nch)
            LOAD_CHUNK(kt + STAGES - 1, (kt + STAGES - 1) % STAGES);
        cp_commit();

        // ---- compute chunk kt from slot kt%STAGES ----
        const uint32_t st = sbase + (uint32_t)(kt % STAGES) * STAGE_BYTES;
        const uint32_t sb = st + 16384;

#pragma unroll
        for (int ks = 0; ks < 2; ks++) {           // two k16 steps per BK=32
            uint32_t ah[4][4], al[4][4], bh[4][2], bl[4][2];
#pragma unroll
            for (int mt = 0; mt < 4; mt++) {
                const int r0 = warp_m * 64 + mt * 16 + g;
                const int r1 = r0 + 8;
                const int c0 = ks * 2, c1 = ks * 2 + 1;
                ah[mt][0] = lds32(tile_addr(st, r0, c0) + tg * 4);
                ah[mt][1] = lds32(tile_addr(st, r1, c0) + tg * 4);
                ah[mt][2] = lds32(tile_addr(st, r0, c1) + tg * 4);
                ah[mt][3] = lds32(tile_addr(st, r1, c1) + tg * 4);
                al[mt][0] = lds32(tile_addr(st, r0, c0 + 4) + tg * 4);
                al[mt][1] = lds32(tile_addr(st, r1, c0 + 4) + tg * 4);
                al[mt][2] = lds32(tile_addr(st, r0, c1 + 4) + tg * 4);
                al[mt][3] = lds32(tile_addr(st, r1, c1 + 4) + tg * 4);
            }
#pragma unroll
            for (int nt = 0; nt < 4; nt++) {
                const int nr = warp_n * 32 + nt * 8 + g;
                const int c0 = ks * 2, c1 = ks * 2 + 1;
                bh[nt][0] = lds32(tile_addr(sb, nr, c0) + tg * 4);
                bh[nt][1] = lds32(tile_addr(sb, nr, c1) + tg * 4);
                bl[nt][0] = lds32(tile_addr(sb, nr, c0 + 4) + tg * 4);
                bl[nt][1] = lds32(tile_addr(sb, nr, c1 + 4) + tg * 4);
            }
#pragma unroll
            for (int mt = 0; mt < 4; mt++)
#pragma unroll
                for (int nt = 0; nt < 4; nt++) {
                    mma_16816(acc[mt][nt], ah[mt], bh[nt]);   // hi*hi
                    mma_16816(acc[mt][nt], ah[mt], bl[nt]);   // hi*lo
                    mma_16816(acc[mt][nt], al[mt], bh[nt]);   // lo*hi
                }
        }
        __syncthreads();
    }

    // -------------------- epilogue --------------------
#pragma unroll
    for (int nt = 0; nt < 4; nt++) {
        const int col = n_base + warp_n * 32 + nt * 8 + tg * 2;
        const float2 bv = *(const float2*)(bias + col);
#pragma unroll
        for (int mt = 0; mt < 4; mt++) {
            const int r0 = m_base + warp_m * 64 + mt * 16 + g;
#pragma unroll
            for (int hr = 0; hr < 2; hr++) {
                const int row = r0 + hr * 8;
                float v0 = acc[mt][nt][hr * 2 + 0] + bv.x;
                float v1 = acc[mt][nt][hr * 2 + 1] + bv.y;
                const size_t off = (size_t)row * Ntot + col;

                if (MODE == 0) {
                    v0 = tanhf(v0); v1 = tanhf(v1);
                    write_hl(OutHi, OutLo, off, v0, v1);
                } else if (MODE == 1) {
                    float2 yv = *(const float2*)(Yin + off);
                    float2 kk; kk.x = v0; kk.y = v1;
                    *(float2*)(OutF + off) = kk;             // k1
                    float y0n = fmaf(DT_F, v0, yv.x);
                    float y1n = fmaf(DT_F, v1, yv.y);
                    write_hl(OutHi, OutLo, off, y0n, y1n);   // ytmp
                } else {
                    float2 yv = *(const float2*)(Yin + off);
                    float2 kv = *(const float2*)(K1v + off);
                    const float hh = 0.5f * DT_F;
                    float y0n = fmaf(hh, kv.x + v0, yv.x);
                    float y1n = fmaf(hh, kv.y + v1, yv.y);
                    float2 r; r.x = y0n; r.y = y1n;
                    *(float2*)(OutF + off) = r;              // y (fp32)
                    write_hl(OutHi, OutLo, off, y0n, y1n);   // y (hi/lo)
                }
            }
        }
    }
#undef LOAD_CHUNK
}

// ---------------------------------------------------------------------------
// Launch: init (split y0, transpose+split weights), then 10 Heun steps.
// ---------------------------------------------------------------------------
extern "C" void kernel_launch(void* const* d_in, const int* in_sizes, int n_in,
                              void* d_out, int out_size)
{
    const float* y0 = (const float*)d_in[0];
    const float* W1 = (const float*)d_in[1];
    const float* b1 = (const float*)d_in[2];
    const float* W2 = (const float*)d_in[3];
    const float* b2 = (const float*)d_in[4];
    float* out = (float*)d_out;

    float *yv, *k1;
    __half *yh, *yl, *yth, *ytl, *hh, *hl, *w1h, *w1l, *w2h, *w2l;
    void* p;
    cudaGetSymbolAddress(&p, g_y);   yv  = (float*)p;
    cudaGetSymbolAddress(&p, g_k1);  k1  = (float*)p;
    cudaGetSymbolAddress(&p, g_yh);  yh  = (__half*)p;
    cudaGetSymbolAddress(&p, g_yl);  yl  = (__half*)p;
    cudaGetSymbolAddress(&p, g_yth); yth = (__half*)p;
    cudaGetSymbolAddress(&p, g_ytl); ytl = (__half*)p;
    cudaGetSymbolAddress(&p, g_hh);  hh  = (__half*)p;
    cudaGetSymbolAddress(&p, g_hl);  hl  = (__half*)p;
    cudaGetSymbolAddress(&p, g_w1h); w1h = (__half*)p;
    cudaGetSymbolAddress(&p, g_w1l); w1l = (__half*)p;
    cudaGetSymbolAddress(&p, g_w2h); w2h = (__half*)p;
    cudaGetSymbolAddress(&p, g_w2l); w2l = (__half*)p;

    cudaFuncSetAttribute((const void*)gemm_hmma<0>, cudaFuncAttributeMaxDynamicSharedMemorySize, SMEM_BYTES);
    cudaFuncSetAttribute((const void*)gemm_hmma<1>, cudaFuncAttributeMaxDynamicSharedMemorySize, SMEM_BYTES);
    cudaFuncSetAttribute((const void*)gemm_hmma<2>, cudaFuncAttributeMaxDynamicSharedMemorySize, SMEM_BYTES);

    // y = y0 (fp32 + hi/lo)
    {
        int n4 = (int)(NY / 4);
        split_init<<<(n4 + 255) / 256, 256>>>((const float4*)y0, yv, yh, yl, n4);
    }
    // W1T (hi/lo) : [H][D];  W2T (hi/lo) : [D][H]
    transpose_split<<<dim3(HDIM / 32, DDIM / 32), dim3(32, 8)>>>(W1, w1h, w1l, DDIM, HDIM);
    transpose_split<<<dim3(DDIM / 32, HDIM / 32), dim3(32, 8)>>>(W2, w2h, w2l, HDIM, DDIM);

    const dim3 blk(NTHREADS);
    const dim3 gridH(HDIM / BN, BATCH / BM);   // 16 x 64
    const dim3 gridD(DDIM / BN, BATCH / BM);   //  4 x 64

    for (int s = 0; s < N_STEPS; s++) {
        // h = tanh(y @ W1 + b1)
        gemm_hmma<0><<<gridH, blk, SMEM_BYTES>>>(yh, yl, w1h, w1l, b1,
                                                 nullptr, nullptr, nullptr, hh, hl,
                                                 BATCH, HDIM, DDIM);
        // k1 = h @ W2 + b2 ;  ytmp = y + dt*k1
        gemm_hmma<1><<<gridD, blk, SMEM_BYTES>>>(hh, hl, w2h, w2l, b2,
                                                 yv, nullptr, k1, yth, ytl,
                                                 BATCH, DDIM, HDIM);
        // h = tanh(ytmp @ W1 + b1)
        gemm_hmma<0><<<gridH, blk, SMEM_BYTES>>>(yth, ytl, w1h, w1l, b1,
                                                 nullptr, nullptr, nullptr, hh, hl,
                                                 BATCH, HDIM, DDIM);
        // y = y + 0.5*dt*(k1 + (h @ W2 + b2))   (last step writes d_out fp32)
        float* ydst = (s == N_STEPS - 1) ? out : yv;
        gemm_hmma<2><<<gridD, blk, SMEM_BYTES>>>(hh, hl, w2h, w2l, b2,
                                                 yv, k1, ydst, yh, yl,
                                                 BATCH, DDIM, HDIM);
    }
}